// round 8
// baseline (speedup 1.0000x reference)
#include <cuda_runtime.h>
#include <math.h>

#define N_NODES 10000
#define C_IN 128
#define D_OUT 20
#define KNN_K 16
#define FULLM 0xffffffffu

#define KNN_TPB 512                // threads per knn block
#define WARPS_PB (KNN_TPB / 32)    // 16 warps
#define QPW 2                      // queries per warp
#define QPB (WARPS_PB * QPW)       // 32 queries per block
#define TC 512                     // candidate tile
#define EPAD 22                    // row stride floats: 20 dims + sq at [20] + pad

// ---------------- scratch (static device globals; no allocs) ----------------
__device__ float g_h[N_NODES * D_OUT];
__device__ float g_emb[N_NODES * D_OUT];
__device__ float g_embn[N_NODES * D_OUT];
__device__ float g_sqe[N_NODES];
__device__ float4 g_pos4[N_NODES];         // {x, y, z, sq}
__device__ float g_mu[D_OUT];
__device__ float g_rinv[D_OUT];
__device__ int   g_idx_emb[N_NODES * KNN_K];
__device__ int   g_idx_pos[N_NODES * KNN_K];

__device__ __forceinline__ float inf_f() { return __int_as_float(0x7f800000); }

// ---------------- 1) linear: h = x @ W + b ----------------
__global__ void k_linear(const float* __restrict__ x, const float* __restrict__ W,
                         const float* __restrict__ b) {
    int t = blockIdx.x * blockDim.x + threadIdx.x;
    if (t >= N_NODES * D_OUT) return;
    int i = t / D_OUT;
    int d = t % D_OUT;
    const float* xr = x + (size_t)i * C_IN;
    float acc = 0.f;
#pragma unroll 8
    for (int c = 0; c < C_IN; ++c) acc = fmaf(xr[c], W[c * D_OUT + d], acc);
    g_h[t] = acc + b[d];
}

// ---------------- 2) batchnorm stats (deterministic) ----------------
__global__ void k_stats() {
    __shared__ float ss[256];
    __shared__ float sq[256];
    int d = blockIdx.x;
    int tid = threadIdx.x;
    float s = 0.f, q = 0.f;
    for (int i = tid; i < N_NODES; i += 256) {
        float v = g_h[i * D_OUT + d];
        s += v;
        q = fmaf(v, v, q);
    }
    ss[tid] = s; sq[tid] = q;
    __syncthreads();
    for (int o = 128; o > 0; o >>= 1) {
        if (tid < o) { ss[tid] += ss[tid + o]; sq[tid] += sq[tid + o]; }
        __syncthreads();
    }
    if (tid == 0) {
        float mu = ss[0] / (float)N_NODES;
        float var = sq[0] / (float)N_NODES - mu * mu;
        g_mu[d] = mu;
        g_rinv[d] = 1.f / sqrtf(var + 1e-5f);
    }
}

// ---------------- 3) emb = relu(bn(h)); embn = emb + noise*1e-4 ----------------
__global__ void k_emb(const float* __restrict__ noise, const float* __restrict__ gamma,
                      const float* __restrict__ beta) {
    int t = blockIdx.x * blockDim.x + threadIdx.x;
    if (t >= N_NODES * D_OUT) return;
    int d = t % D_OUT;
    float e = (g_h[t] - g_mu[d]) * g_rinv[d] * gamma[d] + beta[d];
    e = fmaxf(e, 0.f);
    g_emb[t] = e;
    g_embn[t] = e + noise[t] * 1e-4f;
}

// ---------------- 4) row squared norms; build padded pos4 ----------------
// pos squared-norm mimics jnp.sum(pos*pos, axis=1): separately-rounded squares,
// left-to-right reduction, NO fma contraction (bit-match with reference).
__global__ void k_sqn(const float* __restrict__ pos) {
    int i = blockIdx.x * blockDim.x + threadIdx.x;
    if (i >= N_NODES) return;
    float s = 0.f;
#pragma unroll
    for (int d = 0; d < D_OUT; ++d) {
        float v = g_emb[i * D_OUT + d];
        s = fmaf(v, v, s);
    }
    g_sqe[i] = s;
    float p0 = pos[i * 3 + 0], p1 = pos[i * 3 + 1], p2 = pos[i * 3 + 2];
    float s0 = __fmul_rn(p0, p0);
    float s1 = __fmul_rn(p1, p1);
    float s2 = __fmul_rn(p2, p2);
    float psq = __fadd_rn(__fadd_rn(s0, s1), s2);
    g_pos4[i] = make_float4(p0, p1, p2, psq);
}

// ---------------- warp-distributed top-k ----------------
// lane r holds the r-th smallest (d2, idx); lanes >=16 overflow. All control
// flow warp-uniform; exact (d2, idx) lexicographic order -> insert-order
// independent selection.
__device__ __forceinline__ bool lt_pair(float d2a, int ia, float d2b, int ib) {
    return (d2a < d2b) || (d2a == d2b && ia < ib);
}

__device__ __forceinline__ void warp_hits(unsigned mask, float d2, int jj, int lane,
                                          float& kd, int& ki, float& kth_d, int& kth_i) {
    while (mask) {
        int src = __ffs(mask) - 1;
        mask &= mask - 1;
        float dn = __shfl_sync(FULLM, d2, src);
        int   in = __shfl_sync(FULLM, jj, src);
        if (lt_pair(dn, in, kth_d, kth_i)) {
            bool p = lt_pair(dn, in, kd, ki);
            unsigned pm = __ballot_sync(FULLM, p);
            int pos = __ffs(pm) - 1;
            float kdu = __shfl_up_sync(FULLM, kd, 1);
            int   kiu = __shfl_up_sync(FULLM, ki, 1);
            if (p) {
                kd = (lane == pos) ? dn : kdu;
                ki = (lane == pos) ? in : kiu;
            }
            kth_d = __shfl_sync(FULLM, kd, 15);
            kth_i = __shfl_sync(FULLM, ki, 15);
        }
    }
}

// ---------------- 5a) emb knn: QPW=2, query vecs in smem (broadcast reads) ----------------
__global__ void __launch_bounds__(KNN_TPB, 2) k_knn_emb(const float* __restrict__ feat,
                                                        const float* __restrict__ sqn,
                                                        int* __restrict__ out_idx) {
    __shared__ float s_feat[TC * EPAD];                 // [c][0..19]=dims, [c][20]=sq
    __shared__ float s_qv[WARPS_PB * QPW * D_OUT];      // per-warp query vectors
    const int lane = threadIdx.x & 31;
    const int wid = threadIdx.x >> 5;
    const int qbase = blockIdx.x * QPB + wid * QPW;
    const bool qok = (qbase < N_NODES);                 // warp-uniform (QPB even, N even)

    // warp loads its 2 query vectors into smem (contiguous in feat)
    if (qok && lane < QPW * D_OUT)
        s_qv[wid * (QPW * D_OUT) + lane] = feat[(size_t)qbase * D_OUT + lane];
    if (lane >= QPW * D_OUT && qok) {
        int l2 = lane - QPW * D_OUT;                    // lanes 40..? none (QPW*D_OUT=40>31)
        (void)l2;
    }
    // QPW*D_OUT = 40 > 32: second chunk
    if (qok && lane + 32 < QPW * D_OUT)
        s_qv[wid * (QPW * D_OUT) + lane + 32] = feat[(size_t)qbase * D_OUT + lane + 32];

    float qsq0 = 0.f, qsq1 = 0.f;
    if (qok) { qsq0 = sqn[qbase]; qsq1 = sqn[qbase + 1]; }

    // volatile broadcast pointers (prevents hoisting 40 floats into regs)
    const volatile float2* qv0 = (const volatile float2*)&s_qv[wid * (QPW * D_OUT)];
    const volatile float2* qv1 = qv0 + (D_OUT / 2);

    float kd0 = inf_f(), kd1 = inf_f();
    int ki0 = 0x7fffffff, ki1 = 0x7fffffff;
    float kth_d0 = inf_f(), kth_d1 = inf_f();
    int kth_i0 = 0x7fffffff, kth_i1 = 0x7fffffff;

    for (int base = 0; base < N_NODES; base += TC) {
        const int cnt = min(TC, N_NODES - base);
        __syncthreads();
        for (int idx = threadIdx.x; idx < cnt * D_OUT; idx += KNN_TPB) {
            int c = idx / D_OUT, d = idx - c * D_OUT;
            s_feat[c * EPAD + d] = feat[(size_t)(base + c) * D_OUT + d];
        }
        for (int idx = threadIdx.x; idx < cnt; idx += KNN_TPB)
            s_feat[idx * EPAD + D_OUT] = sqn[base + idx];
        __syncthreads();

        if (qok) {
            for (int c0 = 0; c0 < cnt; c0 += 64) {
                const int ca = c0 + lane;
                const int cb = ca + 32;
                const bool bada = (ca >= cnt);
                const bool badb = (cb >= cnt);
                const int csa = bada ? 0 : ca;
                const int csb = badb ? 0 : cb;
                const int ja = base + csa;
                const int jb = base + csb;
                const float ssqa = s_feat[csa * EPAD + D_OUT];
                const float ssqb = s_feat[csb * EPAD + D_OUT];
                const float2* ra = (const float2*)&s_feat[csa * EPAD];
                const float2* rb = (const float2*)&s_feat[csb * EPAD];

                float a00 = 0.f, a01 = 0.f, a10 = 0.f, a11 = 0.f;
#pragma unroll
                for (int kk = 0; kk < D_OUT / 2; ++kk) {
                    float2 va = ra[kk];
                    float2 vb = rb[kk];
                    float q0x = qv0[kk].x, q0y = qv0[kk].y;   // broadcast LDS
                    float q1x = qv1[kk].x, q1y = qv1[kk].y;
                    a00 = fmaf(q0x, va.x, a00);
                    a00 = fmaf(q0y, va.y, a00);
                    a01 = fmaf(q0x, vb.x, a01);
                    a01 = fmaf(q0y, vb.y, a01);
                    a10 = fmaf(q1x, va.x, a10);
                    a10 = fmaf(q1y, va.y, a10);
                    a11 = fmaf(q1x, vb.x, a11);
                    a11 = fmaf(q1y, vb.y, a11);
                }
                // query 0
                {
                    const int q = qbase;
                    float d2a = fmaf(-2.f, a00, qsq0 + ssqa);
                    float d2b = fmaf(-2.f, a01, qsq0 + ssqb);
                    int jja = ja, jjb = jb;
                    if (bada || ja == q) { d2a = inf_f(); jja = 0x7fffffff; }
                    if (badb || jb == q) { d2b = inf_f(); jjb = 0x7fffffff; }
                    unsigned m0 = __ballot_sync(FULLM, lt_pair(d2a, jja, kth_d0, kth_i0));
                    unsigned m1 = __ballot_sync(FULLM, lt_pair(d2b, jjb, kth_d0, kth_i0));
                    if (m0) warp_hits(m0, d2a, jja, lane, kd0, ki0, kth_d0, kth_i0);
                    if (m1) warp_hits(m1, d2b, jjb, lane, kd0, ki0, kth_d0, kth_i0);
                }
                // query 1
                {
                    const int q = qbase + 1;
                    float d2a = fmaf(-2.f, a10, qsq1 + ssqa);
                    float d2b = fmaf(-2.f, a11, qsq1 + ssqb);
                    int jja = ja, jjb = jb;
                    if (bada || ja == q) { d2a = inf_f(); jja = 0x7fffffff; }
                    if (badb || jb == q) { d2b = inf_f(); jjb = 0x7fffffff; }
                    unsigned m0 = __ballot_sync(FULLM, lt_pair(d2a, jja, kth_d1, kth_i1));
                    unsigned m1 = __ballot_sync(FULLM, lt_pair(d2b, jjb, kth_d1, kth_i1));
                    if (m0) warp_hits(m0, d2a, jja, lane, kd1, ki1, kth_d1, kth_i1);
                    if (m1) warp_hits(m1, d2b, jjb, lane, kd1, ki1, kth_d1, kth_i1);
                }
            }
        }
    }
    if (qok && lane < KNN_K) {
        out_idx[qbase * KNN_K + lane] = ki0;
        out_idx[(qbase + 1) * KNN_K + lane] = ki1;
    }
}

// ---------------- 5b) pos knn: QPW=2 in regs, 2 cands/lane ----------------
__global__ void __launch_bounds__(KNN_TPB) k_knn_pos(const float4* __restrict__ p4,
                                                     int* __restrict__ out_idx) {
    __shared__ float4 s_p[TC];
    const int lane = threadIdx.x & 31;
    const int wid = threadIdx.x >> 5;
    const int qbase = blockIdx.x * QPB + wid * QPW;
    const bool qok = (qbase < N_NODES);

    float4 qp0 = make_float4(0.f, 0.f, 0.f, 0.f), qp1 = qp0;
    if (qok) { qp0 = p4[qbase]; qp1 = p4[qbase + 1]; }

    float kd0 = inf_f(), kd1 = inf_f();
    int ki0 = 0x7fffffff, ki1 = 0x7fffffff;
    float kth_d0 = inf_f(), kth_d1 = inf_f();
    int kth_i0 = 0x7fffffff, kth_i1 = 0x7fffffff;

    for (int base = 0; base < N_NODES; base += TC) {
        const int cnt = min(TC, N_NODES - base);
        __syncthreads();
        for (int idx = threadIdx.x; idx < cnt; idx += KNN_TPB)
            s_p[idx] = p4[base + idx];
        __syncthreads();

        if (qok) {
            for (int c0 = 0; c0 < cnt; c0 += 64) {
                const int ca = c0 + lane;
                const int cb = ca + 32;
                const bool bada = (ca >= cnt);
                const bool badb = (cb >= cnt);
                const int csa = bada ? 0 : ca;
                const int csb = badb ? 0 : cb;
                const int ja = base + csa;
                const int jb = base + csb;
                const float4 va = s_p[csa];
                const float4 vb = s_p[csb];
                // query 0
                {
                    const int q = qbase;
                    float a = fmaf(qp0.x, va.x, 0.f);
                    a = fmaf(qp0.y, va.y, a);
                    a = fmaf(qp0.z, va.z, a);
                    float b = fmaf(qp0.x, vb.x, 0.f);
                    b = fmaf(qp0.y, vb.y, b);
                    b = fmaf(qp0.z, vb.z, b);
                    float d2a = __fadd_rn(__fadd_rn(qp0.w, va.w), -__fmul_rn(2.f, a));
                    float d2b = __fadd_rn(__fadd_rn(qp0.w, vb.w), -__fmul_rn(2.f, b));
                    int jja = ja, jjb = jb;
                    if (bada || ja == q) { d2a = inf_f(); jja = 0x7fffffff; }
                    if (badb || jb == q) { d2b = inf_f(); jjb = 0x7fffffff; }
                    unsigned m0 = __ballot_sync(FULLM, lt_pair(d2a, jja, kth_d0, kth_i0));
                    unsigned m1 = __ballot_sync(FULLM, lt_pair(d2b, jjb, kth_d0, kth_i0));
                    if (m0) warp_hits(m0, d2a, jja, lane, kd0, ki0, kth_d0, kth_i0);
                    if (m1) warp_hits(m1, d2b, jjb, lane, kd0, ki0, kth_d0, kth_i0);
                }
                // query 1
                {
                    const int q = qbase + 1;
                    float a = fmaf(qp1.x, va.x, 0.f);
                    a = fmaf(qp1.y, va.y, a);
                    a = fmaf(qp1.z, va.z, a);
                    float b = fmaf(qp1.x, vb.x, 0.f);
                    b = fmaf(qp1.y, vb.y, b);
                    b = fmaf(qp1.z, vb.z, b);
                    float d2a = __fadd_rn(__fadd_rn(qp1.w, va.w), -__fmul_rn(2.f, a));
                    float d2b = __fadd_rn(__fadd_rn(qp1.w, vb.w), -__fmul_rn(2.f, b));
                    int jja = ja, jjb = jb;
                    if (bada || ja == q) { d2a = inf_f(); jja = 0x7fffffff; }
                    if (badb || jb == q) { d2b = inf_f(); jjb = 0x7fffffff; }
                    unsigned m0 = __ballot_sync(FULLM, lt_pair(d2a, jja, kth_d1, kth_i1));
                    unsigned m1 = __ballot_sync(FULLM, lt_pair(d2b, jjb, kth_d1, kth_i1));
                    if (m0) warp_hits(m0, d2a, jja, lane, kd1, ki1, kth_d1, kth_i1);
                    if (m1) warp_hits(m1, d2b, jjb, lane, kd1, ki1, kth_d1, kth_i1);
                }
            }
        }
    }
    if (qok && lane < KNN_K) {
        out_idx[qbase * KNN_K + lane] = ki0;
        out_idx[(qbase + 1) * KNN_K + lane] = ki1;
    }
}

// ---------------- 7) epilogue ----------------
__global__ void k_final(const float* __restrict__ tptr, float* __restrict__ out) {
    const int NK = N_NODES * KNN_K;
    int e = blockIdx.x * blockDim.x + threadIdx.x;
    if (e >= NK) return;
    int i = e / KNN_K;
    int src = g_idx_emb[e];
    float s = 0.f;
#pragma unroll
    for (int d = 0; d < D_OUT; ++d) {
        float df = g_embn[src * D_OUT + d] - g_embn[i * D_OUT + d];
        s = fmaf(df, df, s);
    }
    float dist = sqrtf(s);
    float p = expf(-tptr[0] * dist);
    float fi = (float)i;
    float fs = (float)src;

    out[e] = p;
    out[NK + e] = p;
    out[2 * NK + e] = fi;
    out[3 * NK + e] = fs;
    out[4 * NK + e] = fi;
    out[5 * NK + e] = fs;
    out[6 * NK + e] = (float)g_idx_pos[e];
    out[7 * NK + e] = fi;
    out[8 * NK + e] = fi;
}

// ---------------- launch ----------------
extern "C" void kernel_launch(void* const* d_in, const int* in_sizes, int n_in,
                              void* d_out, int out_size) {
    const float* x     = (const float*)d_in[0];
    const float* pos   = (const float*)d_in[1];
    const float* noise = (const float*)d_in[2];
    const float* W     = (const float*)d_in[3];
    const float* b     = (const float*)d_in[4];
    const float* gamma = (const float*)d_in[5];
    const float* beta  = (const float*)d_in[6];
    const float* t     = (const float*)d_in[7];
    float* out = (float*)d_out;

    int nd = N_NODES * D_OUT;
    k_linear<<<(nd + 255) / 256, 256>>>(x, W, b);
    k_stats<<<D_OUT, 256>>>();
    k_emb<<<(nd + 255) / 256, 256>>>(noise, gamma, beta);
    k_sqn<<<(N_NODES + 255) / 256, 256>>>(pos);

    int* d_idx_emb; cudaGetSymbolAddress((void**)&d_idx_emb, g_idx_emb);
    int* d_idx_pos; cudaGetSymbolAddress((void**)&d_idx_pos, g_idx_pos);
    float* d_emb;   cudaGetSymbolAddress((void**)&d_emb, g_emb);
    float* d_sqe;   cudaGetSymbolAddress((void**)&d_sqe, g_sqe);
    float4* d_pos4; cudaGetSymbolAddress((void**)&d_pos4, g_pos4);

    const int nblk = (N_NODES + QPB - 1) / QPB;   // 313
    k_knn_emb<<<nblk, KNN_TPB>>>(d_emb, d_sqe, d_idx_emb);
    k_knn_pos<<<nblk, KNN_TPB>>>(d_pos4, d_idx_pos);

    const int NK = N_NODES * KNN_K;
    k_final<<<(NK + 255) / 256, 256>>>(t, out);
    (void)in_sizes; (void)n_in; (void)out_size;
}

// round 9
// speedup vs baseline: 1.3335x; 1.3335x over previous
#include <cuda_runtime.h>
#include <math.h>

#define N_NODES 10000
#define C_IN 128
#define D_OUT 20
#define KNN_K 16
#define FULLM 0xffffffffu

#define KNN_TPB 512                // threads per knn block
#define WARPS_PB (KNN_TPB / 32)    // 16 warps == 16 queries per block
#define TC 512                     // candidate tile

// ---------------- scratch (static device globals; no allocs) ----------------
__device__ float g_h[N_NODES * D_OUT];
__device__ float g_emb[N_NODES * D_OUT];
__device__ float g_embn[N_NODES * D_OUT];
__device__ float g_sqe[N_NODES];
__device__ float4 g_pos4[N_NODES];         // {x, y, z, sq}
__device__ float g_mu[D_OUT];
__device__ float g_rinv[D_OUT];
__device__ int   g_idx_emb[N_NODES * KNN_K];
__device__ int   g_idx_pos[N_NODES * KNN_K];

__device__ __forceinline__ float inf_f() { return __int_as_float(0x7f800000); }

// ---------------- 1) linear: h = x @ W + b ----------------
__global__ void k_linear(const float* __restrict__ x, const float* __restrict__ W,
                         const float* __restrict__ b) {
    int t = blockIdx.x * blockDim.x + threadIdx.x;
    if (t >= N_NODES * D_OUT) return;
    int i = t / D_OUT;
    int d = t % D_OUT;
    const float* xr = x + (size_t)i * C_IN;
    float acc = 0.f;
#pragma unroll 8
    for (int c = 0; c < C_IN; ++c) acc = fmaf(xr[c], W[c * D_OUT + d], acc);
    g_h[t] = acc + b[d];
}

// ---------------- 2) batchnorm stats (deterministic) ----------------
__global__ void k_stats() {
    __shared__ float ss[256];
    __shared__ float sq[256];
    int d = blockIdx.x;
    int tid = threadIdx.x;
    float s = 0.f, q = 0.f;
    for (int i = tid; i < N_NODES; i += 256) {
        float v = g_h[i * D_OUT + d];
        s += v;
        q = fmaf(v, v, q);
    }
    ss[tid] = s; sq[tid] = q;
    __syncthreads();
    for (int o = 128; o > 0; o >>= 1) {
        if (tid < o) { ss[tid] += ss[tid + o]; sq[tid] += sq[tid + o]; }
        __syncthreads();
    }
    if (tid == 0) {
        float mu = ss[0] / (float)N_NODES;
        float var = sq[0] / (float)N_NODES - mu * mu;
        g_mu[d] = mu;
        g_rinv[d] = 1.f / sqrtf(var + 1e-5f);
    }
}

// ---------------- 3) fused: emb = relu(bn(h)); embn; sq norms; pos4 ----------------
// Row per thread. BN expression and fma-chain order identical to the previously
// passing split kernels (bit-exact). pos squared-norm mimics jnp.sum(pos*pos):
// separately-rounded squares, left-to-right adds, no contraction.
__global__ void k_emb_sqn(const float* __restrict__ noise, const float* __restrict__ gamma,
                          const float* __restrict__ beta, const float* __restrict__ pos) {
    int i = blockIdx.x * blockDim.x + threadIdx.x;
    if (i >= N_NODES) return;
    float s = 0.f;
#pragma unroll
    for (int d = 0; d < D_OUT; ++d) {
        int t = i * D_OUT + d;
        float e = (g_h[t] - g_mu[d]) * g_rinv[d] * gamma[d] + beta[d];
        e = fmaxf(e, 0.f);
        g_emb[t] = e;
        g_embn[t] = e + noise[t] * 1e-4f;
        s = fmaf(e, e, s);
    }
    g_sqe[i] = s;
    float p0 = pos[i * 3 + 0], p1 = pos[i * 3 + 1], p2 = pos[i * 3 + 2];
    float s0 = __fmul_rn(p0, p0);
    float s1 = __fmul_rn(p1, p1);
    float s2 = __fmul_rn(p2, p2);
    float psq = __fadd_rn(__fadd_rn(s0, s1), s2);
    g_pos4[i] = make_float4(p0, p1, p2, psq);
}

// ---------------- warp-distributed top-k ----------------
// lane r holds the r-th smallest (d2, idx); lanes >=16 overflow. All control
// flow warp-uniform; exact (d2, idx) lexicographic order -> insert-order
// independent selection.
__device__ __forceinline__ bool lt_pair(float d2a, int ia, float d2b, int ib) {
    return (d2a < d2b) || (d2a == d2b && ia < ib);
}

__device__ __forceinline__ void warp_hits(unsigned mask, float d2, int jj, int lane,
                                          float& kd, int& ki, float& kth_d, int& kth_i) {
    while (mask) {
        int src = __ffs(mask) - 1;
        mask &= mask - 1;
        float dn = __shfl_sync(FULLM, d2, src);
        int   in = __shfl_sync(FULLM, jj, src);
        if (lt_pair(dn, in, kth_d, kth_i)) {
            bool p = lt_pair(dn, in, kd, ki);
            unsigned pm = __ballot_sync(FULLM, p);
            int pos = __ffs(pm) - 1;
            float kdu = __shfl_up_sync(FULLM, kd, 1);
            int   kiu = __shfl_up_sync(FULLM, ki, 1);
            if (p) {
                kd = (lane == pos) ? dn : kdu;
                ki = (lane == pos) ? in : kiu;
            }
            kth_d = __shfl_sync(FULLM, kd, 15);
            kth_i = __shfl_sync(FULLM, ki, 15);
        }
    }
}

// ---------------- 4) emb knn: warp per query, dense rows + float4 LDS ----------------
// Dense 20-float rows: with 8-lane LDS.128 phases, banks (c*20 mod 32) over any
// 8 consecutive lanes are {0,20,8,28,16,4,24,12} -> conflict-free.
__global__ void __launch_bounds__(KNN_TPB) k_knn_emb(const float* __restrict__ feat,
                                                     const float* __restrict__ sqn,
                                                     int* __restrict__ out_idx) {
    __shared__ float s_feat[TC * D_OUT];   // 40 KB, dense
    __shared__ float s_sq[TC];
    const int lane = threadIdx.x & 31;
    const int wid = threadIdx.x >> 5;
    const int q = blockIdx.x * WARPS_PB + wid;   // 625*16 == 10000: always valid

    float qv[D_OUT];
#pragma unroll
    for (int d = 0; d < D_OUT; ++d) qv[d] = feat[(size_t)q * D_OUT + d];
    const float qsq = sqn[q];

    float kd = inf_f();  int ki = 0x7fffffff;
    float kth_d = inf_f(); int kth_i = 0x7fffffff;

    for (int base = 0; base < N_NODES; base += TC) {
        const int cnt = min(TC, N_NODES - base);
        __syncthreads();
        // dense linear copy: no per-element division
        {
            const float4* src4 = (const float4*)(feat + (size_t)base * D_OUT);
            float4* dst4 = (float4*)s_feat;
            const int n4 = (cnt * D_OUT) / 4;              // cnt*20 divisible by 4
            for (int idx = threadIdx.x; idx < n4; idx += KNN_TPB)
                dst4[idx] = src4[idx];
        }
        for (int idx = threadIdx.x; idx < cnt; idx += KNN_TPB)
            s_sq[idx] = sqn[base + idx];
        __syncthreads();

        for (int c0 = 0; c0 < cnt; c0 += 64) {
            const int ca = c0 + lane;
            const int cb = ca + 32;
            const bool bada = (ca >= cnt);
            const bool badb = (cb >= cnt);
            const int csa = bada ? 0 : ca;
            const int csb = badb ? 0 : cb;
            const int ja = base + csa;
            const int jb = base + csb;
            const float ssqa = s_sq[csa];
            const float ssqb = s_sq[csb];
            const float4* ra = (const float4*)&s_feat[csa * D_OUT];
            const float4* rb = (const float4*)&s_feat[csb * D_OUT];

            float a0 = 0.f, a1 = 0.f;
#pragma unroll
            for (int kk = 0; kk < D_OUT / 4; ++kk) {
                float4 va = ra[kk];
                float4 vb = rb[kk];
                a0 = fmaf(qv[4 * kk + 0], va.x, a0);
                a0 = fmaf(qv[4 * kk + 1], va.y, a0);
                a0 = fmaf(qv[4 * kk + 2], va.z, a0);
                a0 = fmaf(qv[4 * kk + 3], va.w, a0);
                a1 = fmaf(qv[4 * kk + 0], vb.x, a1);
                a1 = fmaf(qv[4 * kk + 1], vb.y, a1);
                a1 = fmaf(qv[4 * kk + 2], vb.z, a1);
                a1 = fmaf(qv[4 * kk + 3], vb.w, a1);
            }
            float d2a = fmaf(-2.f, a0, qsq + ssqa);
            float d2b = fmaf(-2.f, a1, qsq + ssqb);
            int jja = ja, jjb = jb;
            if (bada || ja == q) { d2a = inf_f(); jja = 0x7fffffff; }
            if (badb || jb == q) { d2b = inf_f(); jjb = 0x7fffffff; }

            unsigned m0 = __ballot_sync(FULLM, lt_pair(d2a, jja, kth_d, kth_i));
            unsigned m1 = __ballot_sync(FULLM, lt_pair(d2b, jjb, kth_d, kth_i));
            if (m0) warp_hits(m0, d2a, jja, lane, kd, ki, kth_d, kth_i);
            if (m1) warp_hits(m1, d2b, jjb, lane, kd, ki, kth_d, kth_i);
        }
    }
    if (lane < KNN_K) out_idx[q * KNN_K + lane] = ki;
}

// ---------------- 5) pos knn: warp per query (R3 structure) ----------------
__global__ void __launch_bounds__(KNN_TPB) k_knn_pos(const float4* __restrict__ p4,
                                                     int* __restrict__ out_idx) {
    __shared__ float4 s_p[TC];
    const int lane = threadIdx.x & 31;
    const int wid = threadIdx.x >> 5;
    const int q = blockIdx.x * WARPS_PB + wid;

    const float4 qp = p4[q];

    float kd = inf_f();  int ki = 0x7fffffff;
    float kth_d = inf_f(); int kth_i = 0x7fffffff;

    for (int base = 0; base < N_NODES; base += TC) {
        const int cnt = min(TC, N_NODES - base);
        __syncthreads();
        for (int idx = threadIdx.x; idx < cnt; idx += KNN_TPB)
            s_p[idx] = p4[base + idx];
        __syncthreads();

        for (int c0 = 0; c0 < cnt; c0 += 64) {
            const int ca = c0 + lane;
            const int cb = ca + 32;
            const bool bada = (ca >= cnt);
            const bool badb = (cb >= cnt);
            const int csa = bada ? 0 : ca;
            const int csb = badb ? 0 : cb;
            const int ja = base + csa;
            const int jb = base + csb;
            const float4 va = s_p[csa];
            const float4 vb = s_p[csb];
            // dot as ascending fma chain; d2 = fl(fl(sqi+sqj) - fl(2*dot))
            float a = fmaf(qp.x, va.x, 0.f);
            a = fmaf(qp.y, va.y, a);
            a = fmaf(qp.z, va.z, a);
            float b = fmaf(qp.x, vb.x, 0.f);
            b = fmaf(qp.y, vb.y, b);
            b = fmaf(qp.z, vb.z, b);
            float d2a = __fadd_rn(__fadd_rn(qp.w, va.w), -__fmul_rn(2.f, a));
            float d2b = __fadd_rn(__fadd_rn(qp.w, vb.w), -__fmul_rn(2.f, b));
            int jja = ja, jjb = jb;
            if (bada || ja == q) { d2a = inf_f(); jja = 0x7fffffff; }
            if (badb || jb == q) { d2b = inf_f(); jjb = 0x7fffffff; }

            unsigned m0 = __ballot_sync(FULLM, lt_pair(d2a, jja, kth_d, kth_i));
            unsigned m1 = __ballot_sync(FULLM, lt_pair(d2b, jjb, kth_d, kth_i));
            if (m0) warp_hits(m0, d2a, jja, lane, kd, ki, kth_d, kth_i);
            if (m1) warp_hits(m1, d2b, jjb, lane, kd, ki, kth_d, kth_i);
        }
    }
    if (lane < KNN_K) out_idx[q * KNN_K + lane] = ki;
}

// ---------------- 6) epilogue ----------------
__global__ void k_final(const float* __restrict__ tptr, float* __restrict__ out) {
    const int NK = N_NODES * KNN_K;
    int e = blockIdx.x * blockDim.x + threadIdx.x;
    if (e >= NK) return;
    int i = e / KNN_K;
    int src = g_idx_emb[e];
    float s = 0.f;
#pragma unroll
    for (int d = 0; d < D_OUT; ++d) {
        float df = g_embn[src * D_OUT + d] - g_embn[i * D_OUT + d];
        s = fmaf(df, df, s);
    }
    float dist = sqrtf(s);
    float p = expf(-tptr[0] * dist);
    float fi = (float)i;
    float fs = (float)src;

    out[e] = p;
    out[NK + e] = p;
    out[2 * NK + e] = fi;
    out[3 * NK + e] = fs;
    out[4 * NK + e] = fi;
    out[5 * NK + e] = fs;
    out[6 * NK + e] = (float)g_idx_pos[e];
    out[7 * NK + e] = fi;
    out[8 * NK + e] = fi;
}

// ---------------- launch ----------------
extern "C" void kernel_launch(void* const* d_in, const int* in_sizes, int n_in,
                              void* d_out, int out_size) {
    const float* x     = (const float*)d_in[0];
    const float* pos   = (const float*)d_in[1];
    const float* noise = (const float*)d_in[2];
    const float* W     = (const float*)d_in[3];
    const float* b     = (const float*)d_in[4];
    const float* gamma = (const float*)d_in[5];
    const float* beta  = (const float*)d_in[6];
    const float* t     = (const float*)d_in[7];
    float* out = (float*)d_out;

    int nd = N_NODES * D_OUT;
    k_linear<<<(nd + 255) / 256, 256>>>(x, W, b);
    k_stats<<<D_OUT, 256>>>();
    k_emb_sqn<<<(N_NODES + 255) / 256, 256>>>(noise, gamma, beta, pos);

    int* d_idx_emb; cudaGetSymbolAddress((void**)&d_idx_emb, g_idx_emb);
    int* d_idx_pos; cudaGetSymbolAddress((void**)&d_idx_pos, g_idx_pos);
    float* d_emb;   cudaGetSymbolAddress((void**)&d_emb, g_emb);
    float* d_sqe;   cudaGetSymbolAddress((void**)&d_sqe, g_sqe);
    float4* d_pos4; cudaGetSymbolAddress((void**)&d_pos4, g_pos4);

    const int nblk = N_NODES / WARPS_PB;   // 625
    k_knn_emb<<<nblk, KNN_TPB>>>(d_emb, d_sqe, d_idx_emb);   // 4th launch -> profiled
    k_knn_pos<<<nblk, KNN_TPB>>>(d_pos4, d_idx_pos);

    const int NK = N_NODES * KNN_K;
    k_final<<<(NK + 255) / 256, 256>>>(t, out);
    (void)in_sizes; (void)n_in; (void)out_size;
}

// round 10
// speedup vs baseline: 1.4447x; 1.0833x over previous
#include <cuda_runtime.h>
#include <math.h>

#define N_NODES 10000
#define C_IN 128
#define D_OUT 20
#define KNN_K 16
#define FULLM 0xffffffffu

#define ETPB 256                   // emb knn threads per block
#define EWPB (ETPB / 32)           // 8 queries per block
#define PTPB 512                   // pos knn threads per block
#define PWPB (PTPB / 32)           // 16 queries per block
#define TC 512                     // candidate tile
#define NFULL ((N_NODES / TC) * TC)   // 9728: candidates covered by full tiles

// ---------------- scratch (static device globals; no allocs) ----------------
__device__ float g_h[N_NODES * D_OUT];
__device__ float g_emb[N_NODES * D_OUT];
__device__ float g_embn[N_NODES * D_OUT];
__device__ float g_sqe[N_NODES];
__device__ float4 g_pos4[N_NODES];         // {x, y, z, sq}
__device__ float g_mu[D_OUT];
__device__ float g_rinv[D_OUT];
__device__ int   g_idx_emb[N_NODES * KNN_K];
__device__ int   g_idx_pos[N_NODES * KNN_K];

__device__ __forceinline__ float inf_f() { return __int_as_float(0x7f800000); }

// ---------------- 1) linear: h = x @ W + b ----------------
__global__ void k_linear(const float* __restrict__ x, const float* __restrict__ W,
                         const float* __restrict__ b) {
    int t = blockIdx.x * blockDim.x + threadIdx.x;
    if (t >= N_NODES * D_OUT) return;
    int i = t / D_OUT;
    int d = t % D_OUT;
    const float* xr = x + (size_t)i * C_IN;
    float acc = 0.f;
#pragma unroll 8
    for (int c = 0; c < C_IN; ++c) acc = fmaf(xr[c], W[c * D_OUT + d], acc);
    g_h[t] = acc + b[d];
}

// ---------------- 2) batchnorm stats (deterministic) ----------------
__global__ void k_stats() {
    __shared__ float ss[256];
    __shared__ float sq[256];
    int d = blockIdx.x;
    int tid = threadIdx.x;
    float s = 0.f, q = 0.f;
    for (int i = tid; i < N_NODES; i += 256) {
        float v = g_h[i * D_OUT + d];
        s += v;
        q = fmaf(v, v, q);
    }
    ss[tid] = s; sq[tid] = q;
    __syncthreads();
    for (int o = 128; o > 0; o >>= 1) {
        if (tid < o) { ss[tid] += ss[tid + o]; sq[tid] += sq[tid + o]; }
        __syncthreads();
    }
    if (tid == 0) {
        float mu = ss[0] / (float)N_NODES;
        float var = sq[0] / (float)N_NODES - mu * mu;
        g_mu[d] = mu;
        g_rinv[d] = 1.f / sqrtf(var + 1e-5f);
    }
}

// ---------------- 3) fused: emb = relu(bn(h)); embn; sq norms; pos4 ----------------
__global__ void k_emb_sqn(const float* __restrict__ noise, const float* __restrict__ gamma,
                          const float* __restrict__ beta, const float* __restrict__ pos) {
    int i = blockIdx.x * blockDim.x + threadIdx.x;
    if (i >= N_NODES) return;
    float s = 0.f;
#pragma unroll
    for (int d = 0; d < D_OUT; ++d) {
        int t = i * D_OUT + d;
        float e = (g_h[t] - g_mu[d]) * g_rinv[d] * gamma[d] + beta[d];
        e = fmaxf(e, 0.f);
        g_emb[t] = e;
        g_embn[t] = e + noise[t] * 1e-4f;
        s = fmaf(e, e, s);
    }
    g_sqe[i] = s;
    float p0 = pos[i * 3 + 0], p1 = pos[i * 3 + 1], p2 = pos[i * 3 + 2];
    float s0 = __fmul_rn(p0, p0);
    float s1 = __fmul_rn(p1, p1);
    float s2 = __fmul_rn(p2, p2);
    float psq = __fadd_rn(__fadd_rn(s0, s1), s2);
    g_pos4[i] = make_float4(p0, p1, p2, psq);
}

// ---------------- warp-distributed top-k ----------------
__device__ __forceinline__ bool lt_pair(float d2a, int ia, float d2b, int ib) {
    return (d2a < d2b) || (d2a == d2b && ia < ib);
}

__device__ __forceinline__ void warp_hits(unsigned mask, float d2, int jj, int lane,
                                          float& kd, int& ki, float& kth_d, int& kth_i) {
    while (mask) {
        int src = __ffs(mask) - 1;
        mask &= mask - 1;
        float dn = __shfl_sync(FULLM, d2, src);
        int   in = __shfl_sync(FULLM, jj, src);
        if (lt_pair(dn, in, kth_d, kth_i)) {
            bool p = lt_pair(dn, in, kd, ki);
            unsigned pm = __ballot_sync(FULLM, p);
            int pos = __ffs(pm) - 1;
            float kdu = __shfl_up_sync(FULLM, kd, 1);
            int   kiu = __shfl_up_sync(FULLM, ki, 1);
            if (p) {
                kd = (lane == pos) ? dn : kdu;
                ki = (lane == pos) ? in : kiu;
            }
            kth_d = __shfl_sync(FULLM, kd, 15);
            kth_i = __shfl_sync(FULLM, ki, 15);
        }
    }
}

// process one candidate (exact pre-filter + distributed insert)
#define EMB_SEL(d2v, jv)                                                          \
    {                                                                             \
        unsigned m = __ballot_sync(FULLM, lt_pair((d2v), (jv), kth_d, kth_i));    \
        if (m) warp_hits(m, (d2v), (jv), lane, kd, ki, kth_d, kth_i);             \
    }

// ---------------- 4) emb knn: warp/query, 4-cand ILP, full/tail split ----------------
// Dense 20-float rows: LDS.128 over 8-lane phases hits banks
// {0,20,8,28,16,4,24,12} -> conflict-free.
__global__ void __launch_bounds__(ETPB, 3) k_knn_emb(const float* __restrict__ feat,
                                                     const float* __restrict__ sqn,
                                                     int* __restrict__ out_idx) {
    __shared__ float s_feat[TC * D_OUT];   // 40 KB dense
    __shared__ float s_sq[TC];
    const int lane = threadIdx.x & 31;
    const int wid = threadIdx.x >> 5;
    const int q = blockIdx.x * EWPB + wid;   // 1250*8 == 10000: always valid

    float qv[D_OUT];
#pragma unroll
    for (int d = 0; d < D_OUT; ++d) qv[d] = feat[(size_t)q * D_OUT + d];
    const float qsq = sqn[q];

    float kd = inf_f();  int ki = 0x7fffffff;
    float kth_d = inf_f(); int kth_i = 0x7fffffff;

    for (int base = 0; base < N_NODES; base += TC) {
        const int cnt = min(TC, N_NODES - base);
        __syncthreads();
        {
            const float4* src4 = (const float4*)(feat + (size_t)base * D_OUT);
            float4* dst4 = (float4*)s_feat;
            const int n4 = (cnt * D_OUT) / 4;
            for (int idx = threadIdx.x; idx < n4; idx += ETPB)
                dst4[idx] = src4[idx];
        }
        for (int idx = threadIdx.x; idx < cnt; idx += ETPB)
            s_sq[idx] = sqn[base + idx];
        __syncthreads();

        if (cnt == TC) {
            // ---- fast path: no bounds clamping, 4 candidates per lane ----
            for (int c0 = 0; c0 < TC; c0 += 128) {
                const int ca = c0 + lane;
                const float4* r0 = (const float4*)&s_feat[ca * D_OUT];
                const float4* r1 = (const float4*)&s_feat[(ca + 32) * D_OUT];
                const float4* r2 = (const float4*)&s_feat[(ca + 64) * D_OUT];
                const float4* r3 = (const float4*)&s_feat[(ca + 96) * D_OUT];
                float a0 = 0.f, a1 = 0.f, a2 = 0.f, a3 = 0.f;
#pragma unroll
                for (int kk = 0; kk < D_OUT / 4; ++kk) {
                    float4 v0 = r0[kk], v1 = r1[kk], v2 = r2[kk], v3 = r3[kk];
                    float q0 = qv[4 * kk + 0], q1 = qv[4 * kk + 1];
                    float q2 = qv[4 * kk + 2], q3 = qv[4 * kk + 3];
                    a0 = fmaf(q0, v0.x, a0); a0 = fmaf(q1, v0.y, a0);
                    a0 = fmaf(q2, v0.z, a0); a0 = fmaf(q3, v0.w, a0);
                    a1 = fmaf(q0, v1.x, a1); a1 = fmaf(q1, v1.y, a1);
                    a1 = fmaf(q2, v1.z, a1); a1 = fmaf(q3, v1.w, a1);
                    a2 = fmaf(q0, v2.x, a2); a2 = fmaf(q1, v2.y, a2);
                    a2 = fmaf(q2, v2.z, a2); a2 = fmaf(q3, v2.w, a2);
                    a3 = fmaf(q0, v3.x, a3); a3 = fmaf(q1, v3.y, a3);
                    a3 = fmaf(q2, v3.z, a3); a3 = fmaf(q3, v3.w, a3);
                }
                int j0 = base + ca, j1 = j0 + 32, j2 = j0 + 64, j3 = j0 + 96;
                float d0 = fmaf(-2.f, a0, qsq + s_sq[ca]);
                float d1 = fmaf(-2.f, a1, qsq + s_sq[ca + 32]);
                float d2 = fmaf(-2.f, a2, qsq + s_sq[ca + 64]);
                float d3 = fmaf(-2.f, a3, qsq + s_sq[ca + 96]);
                if (j0 == q) { d0 = inf_f(); j0 = 0x7fffffff; }
                if (j1 == q) { d1 = inf_f(); j1 = 0x7fffffff; }
                if (j2 == q) { d2 = inf_f(); j2 = 0x7fffffff; }
                if (j3 == q) { d3 = inf_f(); j3 = 0x7fffffff; }
                EMB_SEL(d0, j0)
                EMB_SEL(d1, j1)
                EMB_SEL(d2, j2)
                EMB_SEL(d3, j3)
            }
        } else {
            // ---- tail tile: guarded, 1 candidate per lane ----
            for (int c0 = 0; c0 < cnt; c0 += 32) {
                const int ca = c0 + lane;
                const bool bad = (ca >= cnt);
                const int cs = bad ? 0 : ca;
                int j = base + cs;
                const float4* r = (const float4*)&s_feat[cs * D_OUT];
                float a = 0.f;
#pragma unroll
                for (int kk = 0; kk < D_OUT / 4; ++kk) {
                    float4 v = r[kk];
                    a = fmaf(qv[4 * kk + 0], v.x, a);
                    a = fmaf(qv[4 * kk + 1], v.y, a);
                    a = fmaf(qv[4 * kk + 2], v.z, a);
                    a = fmaf(qv[4 * kk + 3], v.w, a);
                }
                float d2v = fmaf(-2.f, a, qsq + s_sq[cs]);
                if (bad || j == q) { d2v = inf_f(); j = 0x7fffffff; }
                EMB_SEL(d2v, j)
            }
        }
    }
    if (lane < KNN_K) out_idx[q * KNN_K + lane] = ki;
}

// ---------------- 5) pos knn: warp/query, 4-cand ILP, full/tail split ----------------
__global__ void __launch_bounds__(PTPB) k_knn_pos(const float4* __restrict__ p4,
                                                  int* __restrict__ out_idx) {
    __shared__ float4 s_p[TC];
    const int lane = threadIdx.x & 31;
    const int wid = threadIdx.x >> 5;
    const int q = blockIdx.x * PWPB + wid;   // 625*16 == 10000

    const float4 qp = p4[q];

    float kd = inf_f();  int ki = 0x7fffffff;
    float kth_d = inf_f(); int kth_i = 0x7fffffff;

    for (int base = 0; base < N_NODES; base += TC) {
        const int cnt = min(TC, N_NODES - base);
        __syncthreads();
        for (int idx = threadIdx.x; idx < cnt; idx += PTPB)
            s_p[idx] = p4[base + idx];
        __syncthreads();

        if (cnt == TC) {
            for (int c0 = 0; c0 < TC; c0 += 128) {
                const int ca = c0 + lane;
                const float4 v0 = s_p[ca];
                const float4 v1 = s_p[ca + 32];
                const float4 v2 = s_p[ca + 64];
                const float4 v3 = s_p[ca + 96];
                float a0 = fmaf(qp.x, v0.x, 0.f); a0 = fmaf(qp.y, v0.y, a0); a0 = fmaf(qp.z, v0.z, a0);
                float a1 = fmaf(qp.x, v1.x, 0.f); a1 = fmaf(qp.y, v1.y, a1); a1 = fmaf(qp.z, v1.z, a1);
                float a2 = fmaf(qp.x, v2.x, 0.f); a2 = fmaf(qp.y, v2.y, a2); a2 = fmaf(qp.z, v2.z, a2);
                float a3 = fmaf(qp.x, v3.x, 0.f); a3 = fmaf(qp.y, v3.y, a3); a3 = fmaf(qp.z, v3.z, a3);
                float d0 = __fadd_rn(__fadd_rn(qp.w, v0.w), -__fmul_rn(2.f, a0));
                float d1 = __fadd_rn(__fadd_rn(qp.w, v1.w), -__fmul_rn(2.f, a1));
                float d2 = __fadd_rn(__fadd_rn(qp.w, v2.w), -__fmul_rn(2.f, a2));
                float d3 = __fadd_rn(__fadd_rn(qp.w, v3.w), -__fmul_rn(2.f, a3));
                int j0 = base + ca, j1 = j0 + 32, j2 = j0 + 64, j3 = j0 + 96;
                if (j0 == q) { d0 = inf_f(); j0 = 0x7fffffff; }
                if (j1 == q) { d1 = inf_f(); j1 = 0x7fffffff; }
                if (j2 == q) { d2 = inf_f(); j2 = 0x7fffffff; }
                if (j3 == q) { d3 = inf_f(); j3 = 0x7fffffff; }
                EMB_SEL(d0, j0)
                EMB_SEL(d1, j1)
                EMB_SEL(d2, j2)
                EMB_SEL(d3, j3)
            }
        } else {
            for (int c0 = 0; c0 < cnt; c0 += 32) {
                const int ca = c0 + lane;
                const bool bad = (ca >= cnt);
                const int cs = bad ? 0 : ca;
                int j = base + cs;
                const float4 v = s_p[cs];
                float a = fmaf(qp.x, v.x, 0.f);
                a = fmaf(qp.y, v.y, a);
                a = fmaf(qp.z, v.z, a);
                float d2v = __fadd_rn(__fadd_rn(qp.w, v.w), -__fmul_rn(2.f, a));
                if (bad || j == q) { d2v = inf_f(); j = 0x7fffffff; }
                EMB_SEL(d2v, j)
            }
        }
    }
    if (lane < KNN_K) out_idx[q * KNN_K + lane] = ki;
}

// ---------------- 6) epilogue ----------------
__global__ void k_final(const float* __restrict__ tptr, float* __restrict__ out) {
    const int NK = N_NODES * KNN_K;
    int e = blockIdx.x * blockDim.x + threadIdx.x;
    if (e >= NK) return;
    int i = e / KNN_K;
    int src = g_idx_emb[e];
    float s = 0.f;
#pragma unroll
    for (int d = 0; d < D_OUT; ++d) {
        float df = g_embn[src * D_OUT + d] - g_embn[i * D_OUT + d];
        s = fmaf(df, df, s);
    }
    float dist = sqrtf(s);
    float p = expf(-tptr[0] * dist);
    float fi = (float)i;
    float fs = (float)src;

    out[e] = p;
    out[NK + e] = p;
    out[2 * NK + e] = fi;
    out[3 * NK + e] = fs;
    out[4 * NK + e] = fi;
    out[5 * NK + e] = fs;
    out[6 * NK + e] = (float)g_idx_pos[e];
    out[7 * NK + e] = fi;
    out[8 * NK + e] = fi;
}

// ---------------- launch ----------------
extern "C" void kernel_launch(void* const* d_in, const int* in_sizes, int n_in,
                              void* d_out, int out_size) {
    const float* x     = (const float*)d_in[0];
    const float* pos   = (const float*)d_in[1];
    const float* noise = (const float*)d_in[2];
    const float* W     = (const float*)d_in[3];
    const float* b     = (const float*)d_in[4];
    const float* gamma = (const float*)d_in[5];
    const float* beta  = (const float*)d_in[6];
    const float* t     = (const float*)d_in[7];
    float* out = (float*)d_out;

    int nd = N_NODES * D_OUT;
    k_linear<<<(nd + 255) / 256, 256>>>(x, W, b);
    k_stats<<<D_OUT, 256>>>();
    k_emb_sqn<<<(N_NODES + 255) / 256, 256>>>(noise, gamma, beta, pos);

    int* d_idx_emb; cudaGetSymbolAddress((void**)&d_idx_emb, g_idx_emb);
    int* d_idx_pos; cudaGetSymbolAddress((void**)&d_idx_pos, g_idx_pos);
    float* d_emb;   cudaGetSymbolAddress((void**)&d_emb, g_emb);
    float* d_sqe;   cudaGetSymbolAddress((void**)&d_sqe, g_sqe);
    float4* d_pos4; cudaGetSymbolAddress((void**)&d_pos4, g_pos4);

    k_knn_emb<<<N_NODES / EWPB, ETPB>>>(d_emb, d_sqe, d_idx_emb);   // 4th launch -> profiled
    k_knn_pos<<<N_NODES / PWPB, PTPB>>>(d_pos4, d_idx_pos);

    const int NK = N_NODES * KNN_K;
    k_final<<<(NK + 255) / 256, 256>>>(t, out);
    (void)in_sizes; (void)n_in; (void)out_size;
}